// round 2
// baseline (speedup 1.0000x reference)
#include <cuda_runtime.h>
#include <cuda_bf16.h>
#include <cstdint>

// ---------------- problem constants ----------------
#define HW    112
#define IMG   (HW*HW)          // 12544
#define NB    32
#define CIN   128
#define COUT  256
#define NPOS  (NB*IMG)         // 401408
#define KTOT  1152             // 3*3*128

// ---------------- scratch ( __device__ globals, no mallocs ) ----------------
__device__ __nv_bfloat16 g_xhi[(size_t)NPOS * CIN];
__device__ __nv_bfloat16 g_xlo[(size_t)NPOS * CIN];
__device__ __nv_bfloat16 g_wbin[(size_t)COUT * KTOT];   // [co][k], k = tap*128 + c

// ---------------- helpers (base ISA only: sm_80-level PTX) ----------------
__device__ __forceinline__ uint32_t smem_to_u32(const void* p) {
    uint32_t a;
    asm("{ .reg .u64 t; cvta.to.shared.u64 t, %1; cvt.u32.u64 %0, t; }" : "=r"(a) : "l"(p));
    return a;
}

__device__ __forceinline__ void cp16(uint32_t dst, const void* src, bool pred) {
    int sz = pred ? 16 : 0;     // src-size 0 -> 16B of zeros (zfill)
    asm volatile("cp.async.cg.shared.global [%0], [%1], 16, %2;"
                 :: "r"(dst), "l"(src), "r"(sz) : "memory");
}

#define CP_COMMIT() asm volatile("cp.async.commit_group;" ::: "memory")
#define CP_WAIT1()  asm volatile("cp.async.wait_group 1;" ::: "memory")

__device__ __forceinline__ void ldsm4(uint32_t* r, uint32_t addr) {
    asm volatile("ldmatrix.sync.aligned.m8n8.x4.shared.b16 {%0,%1,%2,%3}, [%4];"
                 : "=r"(r[0]), "=r"(r[1]), "=r"(r[2]), "=r"(r[3]) : "r"(addr));
}

__device__ __forceinline__ void mma16816(float* c, const uint32_t* a,
                                         uint32_t b0, uint32_t b1) {
    asm volatile(
        "mma.sync.aligned.m16n8k16.row.col.f32.bf16.bf16.f32 "
        "{%0,%1,%2,%3}, {%4,%5,%6,%7}, {%8,%9}, {%0,%1,%2,%3};"
        : "+f"(c[0]), "+f"(c[1]), "+f"(c[2]), "+f"(c[3])
        : "r"(a[0]), "r"(a[1]), "r"(a[2]), "r"(a[3]), "r"(b0), "r"(b1));
}

// ---------------- SMEM layout ----------------
// buffer b (0/1) at b*49152: A0 16KB | A1 16KB | B 16KB
// rows are 128 bytes (64 bf16), SW128-style XOR swizzle (16B unit ^ (row&7))
static constexpr int BUF_BYTES = 49152;
static constexpr int A_SUB     = 16384;
static constexpr int B_OFF     = 32768;
static constexpr int DYN_SMEM  = 2 * BUF_BYTES;   // 98304

// ---------------- precompute kernels ----------------
__global__ void binarize_kernel(const float* __restrict__ w) {
    int i = blockIdx.x * blockDim.x + threadIdx.x;
    if (i >= COUT * KTOT) return;
    int k  = i >> 8;       // / 256  (co is fastest dim in HWIO)
    int co = i & 255;
    float v = w[i];
    float s = (v > 0.f) ? 1.f : ((v < 0.f) ? -1.f : 0.f);
    g_wbin[co * KTOT + k] = __float2bfloat16(s);
}

__global__ void split_kernel(const float4* __restrict__ x) {
    int i = blockIdx.x * blockDim.x + threadIdx.x;
    if (i >= (NPOS * CIN) / 4) return;
    float4 v = x[i];
    __nv_bfloat16 h0 = __float2bfloat16(v.x);
    __nv_bfloat16 h1 = __float2bfloat16(v.y);
    __nv_bfloat16 h2 = __float2bfloat16(v.z);
    __nv_bfloat16 h3 = __float2bfloat16(v.w);
    __nv_bfloat16 l0 = __float2bfloat16(v.x - __bfloat162float(h0));
    __nv_bfloat16 l1 = __float2bfloat16(v.y - __bfloat162float(h1));
    __nv_bfloat16 l2 = __float2bfloat16(v.z - __bfloat162float(h2));
    __nv_bfloat16 l3 = __float2bfloat16(v.w - __bfloat162float(h3));
    ushort4 hv = make_ushort4(__bfloat16_as_ushort(h0), __bfloat16_as_ushort(h1),
                              __bfloat16_as_ushort(h2), __bfloat16_as_ushort(h3));
    ushort4 lv = make_ushort4(__bfloat16_as_ushort(l0), __bfloat16_as_ushort(l1),
                              __bfloat16_as_ushort(l2), __bfloat16_as_ushort(l3));
    ((ushort4*)g_xhi)[i] = hv;
    ((ushort4*)g_xlo)[i] = lv;
}

// ---------------- main implicit-GEMM conv (mma.sync / HMMA) ----------------
// Grid (NPOS/256, 2). CTA tile: M=256 positions x N=128 output channels.
// 16 warps, warp tile 64x32. K: 2 passes x 9 taps x 2 ch-halves = 36 chunks of 64.
__global__ __launch_bounds__(512, 1)
void conv_kernel(float* __restrict__ out) {
    extern __shared__ char smem[];
    const uint32_t smem_u = smem_to_u32(smem);
    const int tid  = threadIdx.x;
    const int wid  = tid >> 5;
    const int lane = tid & 31;
    const int mt   = blockIdx.x;
    const int nt   = blockIdx.y;

    // ---- per-thread load slots (fixed across the K loop) ----
    // A: 4 slots (2 subtiles x 128 rows x 8 x 16B = 2048 uint4 / 512 thr)
    int cbase[4], hh[4], ww[4];
    uint32_t dstA[4];
#pragma unroll
    for (int j = 0; j < 4; ++j) {
        int s = tid + j * 512;
        int t = s >> 10;
        int r = (s >> 3) & 127;
        int u = s & 7;
        int p = mt * 256 + t * 128 + r;
        int n = p / IMG;
        int rem = p - n * IMG;
        int h = rem / HW;
        int w = rem - h * HW;
        hh[j] = h; ww[j] = w;
        cbase[j] = ((n * HW + h) * HW + w) * CIN + u * 8;
        dstA[j]  = t * A_SUB + r * 128 + ((u ^ (r & 7)) << 4);
    }
    // B: 2 slots (128 rows x 8 x 16B = 1024 uint4 / 512 thr)
    int bsrc[2];
    uint32_t dstB[2];
#pragma unroll
    for (int j = 0; j < 2; ++j) {
        int s = tid + j * 512;
        int r = s >> 3;
        int u = s & 7;
        bsrc[j] = (nt * 128 + r) * KTOT + u * 8;
        dstB[j] = B_OFF + r * 128 + ((u ^ (r & 7)) << 4);
    }

    // ---- warp tiling ----
    const int wm = (wid & 3) * 64;    // m offset within 256
    const int wn = (wid >> 2) * 32;   // n offset within 128
    const int at = wm >> 7;           // A subtile (0/1)
    const int am = wm & 127;          // m within subtile

    float acc[4][4][4];
#pragma unroll
    for (int i = 0; i < 4; ++i)
#pragma unroll
        for (int j = 0; j < 4; ++j)
#pragma unroll
            for (int q = 0; q < 4; ++q) acc[i][j][q] = 0.f;

    // ---- async load of one K-chunk ----
    auto issue_loads = [&](int it, int buf) {
        int pass = it / 18;
        int rem2 = it - pass * 18;
        int tap  = rem2 >> 1;
        int chh  = rem2 & 1;
        int kh = tap / 3, kw = tap - kh * 3;
        const __nv_bfloat16* __restrict__ xsrc = pass ? g_xlo : g_xhi;
        const int doff = ((kh - 1) * HW + (kw - 1)) * CIN + chh * 64;
        const uint32_t bb = smem_u + buf * BUF_BYTES;
#pragma unroll
        for (int j = 0; j < 4; ++j) {
            unsigned h2 = (unsigned)(hh[j] + kh - 1);
            unsigned w2 = (unsigned)(ww[j] + kw - 1);
            bool ok = (h2 < (unsigned)HW) && (w2 < (unsigned)HW);
            cp16(bb + dstA[j], xsrc + cbase[j] + doff, ok);
        }
        const int woff = tap * CIN + chh * 64;
#pragma unroll
        for (int j = 0; j < 2; ++j)
            cp16(bb + dstB[j], g_wbin + bsrc[j] + woff, true);
    };

    issue_loads(0, 0);
    CP_COMMIT();

    for (int it = 0; it < 36; ++it) {
        if (it + 1 < 36) issue_loads(it + 1, (it + 1) & 1);
        CP_COMMIT();               // (possibly empty group on last iter)
        CP_WAIT1();                // chunk `it` resident
        __syncthreads();

        const uint32_t bb    = smem_u + (it & 1) * BUF_BYTES;
        const uint32_t Abase = bb + at * A_SUB;
        const uint32_t Bbase = bb + B_OFF;
        const int arow = am + (lane & 15);
        const int brow = wn + (lane & 15);
        const int khi  = (lane >> 4) << 4;   // 0 or 16 bytes

#pragma unroll
        for (int ks = 0; ks < 4; ++ks) {
            const int kb = ks * 32 + khi;
            uint32_t a[4][4];
#pragma unroll
            for (int mf = 0; mf < 4; ++mf) {
                int row = arow + mf * 16;
                uint32_t off = (uint32_t)(row * 128 + kb) ^ (uint32_t)((row & 7) << 4);
                ldsm4(a[mf], Abase + off);
            }
            uint32_t b[2][4];
#pragma unroll
            for (int q = 0; q < 2; ++q) {
                int row = brow + q * 16;
                uint32_t off = (uint32_t)(row * 128 + kb) ^ (uint32_t)((row & 7) << 4);
                ldsm4(b[q], Bbase + off);
            }
#pragma unroll
            for (int mf = 0; mf < 4; ++mf)
#pragma unroll
                for (int nb = 0; nb < 4; ++nb) {
                    int q = nb >> 1, jj = nb & 1;
                    mma16816(acc[mf][nb], a[mf], b[q][jj], b[q][jj + 2]);
                }
        }
        __syncthreads();
    }

    // ---- epilogue: registers -> gmem ----
    const int r0 = lane >> 2;           // 0..7
    const int c0 = (lane & 3) * 2;      // 0,2,4,6
#pragma unroll
    for (int mf = 0; mf < 4; ++mf) {
        int m  = mt * 256 + wm + mf * 16 + r0;
#pragma unroll
        for (int nb = 0; nb < 4; ++nb) {
            int co = nt * 128 + wn + nb * 8 + c0;
            float* p0 = out + (size_t)m * COUT + co;
            float* p1 = out + (size_t)(m + 8) * COUT + co;
            *(float2*)p0 = make_float2(acc[mf][nb][0], acc[mf][nb][1]);
            *(float2*)p1 = make_float2(acc[mf][nb][2], acc[mf][nb][3]);
        }
    }
}

// ---------------- launch ----------------
extern "C" void kernel_launch(void* const* d_in, const int* in_sizes, int n_in,
                              void* d_out, int out_size) {
    const float* x = (const float*)d_in[0];
    const float* w = (const float*)d_in[1];
    float* out = (float*)d_out;

    cudaFuncSetAttribute(conv_kernel,
                         cudaFuncAttributeMaxDynamicSharedMemorySize, DYN_SMEM);

    binarize_kernel<<<(COUT * KTOT + 255) / 256, 256>>>(w);
    split_kernel<<<(NPOS * CIN / 4) / 256, 256>>>((const float4*)x);
    conv_kernel<<<dim3(NPOS / 256, 2), 512, DYN_SMEM>>>(out);
}